// round 15
// baseline (speedup 1.0000x reference)
#include <cuda_runtime.h>
#include <cstdint>
#include <cstddef>

// ---------------------------------------------------------------------------
// BiLSTM T=1024 B=32 H=256 L=3, 3-gate cell, highway on l>0.
//   zx GEMMs: FFMA2 SGEMM BM128xBN128, 2-stage pipeline, 1 barrier/tile.
//   recurrence: 16 clusters x 8 CTAs (dir x 4-batch group). Wh in registers.
//   h exchange: st.async DSMEM stores with mbarrier complete_tx (R13-proven).
//   R14: k-paired FFMA2 dot — W k-pairs packed at load, h k-pairs loaded
//   directly from [b][k] SMEM; zero pack instructions in the hot loop.
// ---------------------------------------------------------------------------

#define T_LEN 1024
#define BATCH 32
#define ZN    768
#define MROWS (T_LEN*BATCH)
#define H_BYTES_PER_STEP 4096   // 256 cols x 4 batches x 4B into each CTA

__device__ float g_zxf[(size_t)MROWS * ZN];
__device__ float g_zxb[(size_t)MROWS * ZN];
__device__ float g_buf0[(size_t)MROWS * 512];
__device__ float g_buf1[(size_t)MROWS * 512];

__device__ __forceinline__ float sigm(float x) { return 1.f / (1.f + __expf(-x)); }

__device__ __forceinline__ unsigned long long pack2(float lo, float hi) {
    unsigned long long r;
    asm("mov.b64 %0, {%1, %2};" : "=l"(r) : "f"(lo), "f"(hi));
    return r;
}
__device__ __forceinline__ void unpack2(unsigned long long v, float& lo, float& hi) {
    asm("mov.b64 {%0, %1}, %2;" : "=f"(lo), "=f"(hi) : "l"(v));
}
__device__ __forceinline__ void ffma2(unsigned long long& d, unsigned long long a, unsigned long long b) {
    asm("fma.rn.f32x2 %0, %1, %2, %3;" : "=l"(d) : "l"(a), "l"(b), "l"(d));
}
__device__ __forceinline__ void fadd2(unsigned long long& d, unsigned long long a) {
    asm("add.rn.f32x2 %0, %1, %2;" : "=l"(d) : "l"(d), "l"(a));
}
__device__ __forceinline__ unsigned smaddr(const void* p) {
    unsigned a;
    asm("{ .reg .u64 t; cvta.to.shared.u64 t, %1; cvt.u32.u64 %0, t; }" : "=r"(a) : "l"(p));
    return a;
}
__device__ __forceinline__ unsigned mapa_addr(unsigned addr, unsigned rank) {
    unsigned ra;
    asm("mapa.shared::cluster.u32 %0, %1, %2;" : "=r"(ra) : "r"(addr), "r"(rank));
    return ra;
}
// Async DSMEM store: data + 16 tx-bytes delivered to the destination CTA's
// mbarrier. Both addresses live in the SAME destination CTA.
__device__ __forceinline__ void st_async_f128(unsigned raddr, unsigned rmbar, float4 v) {
    asm volatile("st.async.shared::cluster.mbarrier::complete_tx::bytes.v4.f32 "
                 "[%0], {%1,%2,%3,%4}, [%5];"
                 :: "r"(raddr), "f"(v.x), "f"(v.y), "f"(v.z), "f"(v.w), "r"(rmbar)
                 : "memory");
}
__device__ __forceinline__ void mbar_init(unsigned addr, unsigned cnt) {
    asm volatile("mbarrier.init.shared.b64 [%0], %1;" :: "r"(addr), "r"(cnt) : "memory");
}
__device__ __forceinline__ void mbar_expect_tx(unsigned addr, unsigned bytes) {
    asm volatile("mbarrier.arrive.expect_tx.shared.b64 _, [%0], %1;"
                 :: "r"(addr), "r"(bytes) : "memory");
}
__device__ __forceinline__ void mbar_wait(unsigned addr, unsigned parity) {
    unsigned done;
    asm volatile("{ .reg .pred p; "
                 "mbarrier.try_wait.parity.acquire.cta.shared::cta.b64 p, [%1], %2; "
                 "selp.b32 %0, 1, 0, p; }"
                 : "=r"(done) : "r"(addr), "r"(parity) : "memory");
    if (!done) {
        asm volatile("{ .reg .pred P1; "
                     "WL_%=: mbarrier.try_wait.parity.acquire.cta.shared::cta.b64 P1, [%0], %1, 0x989680; "
                     "@P1 bra.uni WD_%=; bra.uni WL_%=; WD_%=: }"
                     :: "r"(addr), "r"(parity) : "memory");
    }
}
#define CLUSTER_SYNC() do { \
    asm volatile("barrier.cluster.arrive.aligned;" ::: "memory"); \
    asm volatile("barrier.cluster.wait.aligned;" ::: "memory"); \
} while (0)

// ------------------------- SGEMM (FFMA2, BM128 x BN128, 1 bar/tile) --------
#define BM 128
#define BN 128
#define BK 16

__global__ __launch_bounds__(256, 2) void sgemm_bias(
    const float* __restrict__ A, const float* __restrict__ B,
    const float* __restrict__ bias, float* __restrict__ C,
    int M, int N, int K)
{
    __shared__ float As[2][BK][BM];
    __shared__ float Bs[2][BK][BN];

    const int bm = blockIdx.y * BM;
    const int bn = blockIdx.x * BN;
    const int tid = threadIdx.x;
    const int tx = tid & 15;
    const int ty = tid >> 4;

    const int ar0 = tid >> 2;
    const int ac4 = tid & 3;
    const int brow = tid >> 4;
    const int bc = tid & 15;

    unsigned long long acc2[4][8];
#pragma unroll
    for (int p = 0; p < 4; p++)
#pragma unroll
        for (int j = 0; j < 8; j++) acc2[p][j] = 0ull;

    const int nIter = K >> 4;

    float4 a0, a1, b0, b1;
    a0 = *(const float4*)(A + (size_t)(bm + ar0) * K + ac4 * 4);
    a1 = *(const float4*)(A + (size_t)(bm + 64 + ar0) * K + ac4 * 4);
    b0 = *(const float4*)(B + (size_t)brow * N + bn + bc * 4);
    b1 = *(const float4*)(B + (size_t)brow * N + bn + 64 + bc * 4);

    for (int it = 0; it < nIter; it++) {
        const int s = it & 1;
        As[s][ac4 * 4 + 0][ar0] = a0.x;
        As[s][ac4 * 4 + 1][ar0] = a0.y;
        As[s][ac4 * 4 + 2][ar0] = a0.z;
        As[s][ac4 * 4 + 3][ar0] = a0.w;
        As[s][ac4 * 4 + 0][64 + ar0] = a1.x;
        As[s][ac4 * 4 + 1][64 + ar0] = a1.y;
        As[s][ac4 * 4 + 2][64 + ar0] = a1.z;
        As[s][ac4 * 4 + 3][64 + ar0] = a1.w;
        *(float4*)&Bs[s][brow][bc * 4]      = b0;
        *(float4*)&Bs[s][brow][64 + bc * 4] = b1;
        __syncthreads();
        if (it + 1 < nIter) {
            int k0 = (it + 1) * BK;
            a0 = *(const float4*)(A + (size_t)(bm + ar0) * K + k0 + ac4 * 4);
            a1 = *(const float4*)(A + (size_t)(bm + 64 + ar0) * K + k0 + ac4 * 4);
            b0 = *(const float4*)(B + (size_t)(k0 + brow) * N + bn + bc * 4);
            b1 = *(const float4*)(B + (size_t)(k0 + brow) * N + bn + 64 + bc * 4);
        }
#pragma unroll
        for (int k = 0; k < BK; k++) {
            ulonglong2 A0 = *(const ulonglong2*)&As[s][k][ty * 8];
            ulonglong2 A1 = *(const ulonglong2*)&As[s][k][ty * 8 + 4];
            float4 bv0 = *(const float4*)&Bs[s][k][tx * 4];
            float4 bv1 = *(const float4*)&Bs[s][k][64 + tx * 4];
            unsigned long long bb;
#define NCOL(J, V)                                                     \
            bb = pack2(V, V);                                          \
            ffma2(acc2[0][J], A0.x, bb); ffma2(acc2[1][J], A0.y, bb);  \
            ffma2(acc2[2][J], A1.x, bb); ffma2(acc2[3][J], A1.y, bb);
            NCOL(0, bv0.x) NCOL(1, bv0.y) NCOL(2, bv0.z) NCOL(3, bv0.w)
            NCOL(4, bv1.x) NCOL(5, bv1.y) NCOL(6, bv1.z) NCOL(7, bv1.w)
#undef NCOL
        }
    }
    float4 bbA = *(const float4*)(bias + bn + tx * 4);
    float4 bbB = *(const float4*)(bias + bn + 64 + tx * 4);
#pragma unroll
    for (int p = 0; p < 4; p++) {
        float lo[8], hi[8];
#pragma unroll
        for (int j = 0; j < 8; j++) unpack2(acc2[p][j], lo[j], hi[j]);
        int row0 = bm + ty * 8 + 2 * p;
        float4 o;
        o.x = lo[0] + bbA.x; o.y = lo[1] + bbA.y; o.z = lo[2] + bbA.z; o.w = lo[3] + bbA.w;
        *(float4*)(C + (size_t)row0 * N + bn + tx * 4) = o;
        o.x = lo[4] + bbB.x; o.y = lo[5] + bbB.y; o.z = lo[6] + bbB.z; o.w = lo[7] + bbB.w;
        *(float4*)(C + (size_t)row0 * N + bn + 64 + tx * 4) = o;
        o.x = hi[0] + bbA.x; o.y = hi[1] + bbA.y; o.z = hi[2] + bbA.z; o.w = hi[3] + bbA.w;
        *(float4*)(C + (size_t)(row0 + 1) * N + bn + tx * 4) = o;
        o.x = hi[4] + bbB.x; o.y = hi[5] + bbB.y; o.z = hi[6] + bbB.z; o.w = hi[7] + bbB.w;
        *(float4*)(C + (size_t)(row0 + 1) * N + bn + 64 + tx * 4) = o;
    }
}

// ------------------------- recurrent scan ----------------------------------
// 128 CTAs, cluster 8. cid = blockIdx.x/8; dir = cid>>3; bg = cid&7.
// CTA rank r owns h-cols [r*32, r*32+32) -> 96 z-cols x 4 batches. 384 thr.
// R14 dot: thread = (jp = tid%48 [j-pair], kc = tid/48 [32-k chunk]).
//   W regs: 32 ull of k-pairs (wA/wB[kk] = (W[k0][j],W[k0+1][j])).
//   h loaded as k-pair ulonglong2 from HS[b][kc][k] (pitch 48/kc, 384/b).
//   acc ull halves = even/odd-k partial sums; merged in reduce via fadd2.
// ZP: [b][kc][jp] (pitch 192/kc, 1552/b), ull per (j,b,kc).
// Sync: st.async + complete_tx mbarrier (R13-proven, no fences).
#define HS_KP 48
#define HS_BP 384
#define ZP_KP 192
#define ZP_BP 1552

__global__ void __cluster_dims__(8, 1, 1) __launch_bounds__(384, 1)
recur14(const float* __restrict__ Whf, const float* __restrict__ Whb,
        const float* __restrict__ h0, const float* __restrict__ c0,
        float* __restrict__ y, float* __restrict__ hn, float* __restrict__ cn,
        int layer)
{
    __shared__ __align__(16) float HS[2][4 * HS_BP]; // h pingpong [b][kc][k]
    __shared__ __align__(16) float ZP[4 * ZP_BP];    // dot partials (ull each)
    __shared__ float ZF[96 * 4];                     // reduced gate sums
    __shared__ __align__(16) float SH[4 * 40];       // nh staging
    __shared__ unsigned long long hmb;               // mbarrier (count 1 + tx)

    const int cid = blockIdx.x >> 3;
    const int dir = cid >> 3;
    const int bg  = cid & 7;
    unsigned rank;
    asm("mov.u32 %0, %%cluster_ctarank;" : "=r"(rank));

    const float* Wh = dir ? Whb : Whf;
    const float* zx = dir ? g_zxb : g_zxf;
    const int tid = threadIdx.x;
    const unsigned hmb_a = smaddr(&hmb);

    const int jp = tid % 48;          // j-pair id (2 j's within one gate)
    const int kc = tid / 48;          // 0..7, k chunk [kc*32, kc*32+32)
    const int rj = tid >> 2;          // reduce: z-col 0..95
    const int rb = tid & 3;
    const int bglob_r = bg * 4 + rb;
    const int zcolr = (rj >> 5) * 256 + (int)rank * 32 + (rj & 31);

    // per-thread DSMEM delta for its push target (rank = lane&7)
    const unsigned anchor = smaddr(&HS[0][0]);
    const unsigned pdel = mapa_addr(anchor, (unsigned)(tid & 7)) - anchor;

    // ---- W slice into registers: k-pairs for 2 j's ----
    const int gate = jp >> 4;                              // 0..2
    const int zc0 = gate * 256 + (int)rank * 32 + (jp & 15) * 2;  // j0 col
    unsigned long long wA[16], wB[16];
#pragma unroll
    for (int kk = 0; kk < 16; kk++) {
        const float* w0 = Wh + (size_t)(kc * 32 + kk * 2) * ZN;
        const float* w1 = w0 + ZN;
        wA[kk] = pack2(__ldg(w0 + zc0),     __ldg(w1 + zc0));      // j0: (k0,k1)
        wB[kk] = pack2(__ldg(w0 + zc0 + 1), __ldg(w1 + zc0 + 1));  // j1
    }

    // ---- init h buffer 0, c, mbarrier ----
    for (int it = tid; it < 4 * 256; it += 384) {
        int b = it >> 8, k = it & 255;
        HS[0][b * HS_BP + (k >> 5) * HS_KP + (k & 31)] = h0[k];
    }
    float creg = 0.f;
    if (tid < 128) creg = c0[(int)rank * 32 + (tid >> 2)];
    if (tid == 0) mbar_init(hmb_a, 1);
    __syncthreads();
    CLUSTER_SYNC();   // inits + HS[0] visible cluster-wide before any st.async

    const int t0 = dir ? (T_LEN - 1) : 0;
    float zxv = __ldg(&zx[((size_t)t0 * BATCH + bglob_r) * ZN + zcolr]);

    for (int tt = 0; tt < T_LEN; tt++) {
        const int t = dir ? (T_LEN - 1 - tt) : tt;

        if (tt) mbar_wait(hmb_a, (tt & 1) ^ 1);   // h[tt&1] fully arrived
        if (tid == 0 && tt + 1 < T_LEN) mbar_expect_tx(hmb_a, H_BYTES_PER_STEP);

        // ---------------- dot: k-paired FFMA2, zero packs -----------------
        const float* hb0 = &HS[tt & 1][kc * HS_KP];
        unsigned long long acc[2][4];
#pragma unroll
        for (int g2 = 0; g2 < 2; g2++)
#pragma unroll
            for (int b = 0; b < 4; b++) acc[g2][b] = 0ull;

#pragma unroll
        for (int b = 0; b < 4; b++) {
            const ulonglong2* hp = (const ulonglong2*)(hb0 + b * HS_BP);
#pragma unroll
            for (int q = 0; q < 8; q++) {
                ulonglong2 hv = hp[q];                     // k pairs (4 k's)
                ffma2(acc[0][b], wA[2 * q],     hv.x);
                ffma2(acc[1][b], wB[2 * q],     hv.x);
                ffma2(acc[0][b], wA[2 * q + 1], hv.y);
                ffma2(acc[1][b], wB[2 * q + 1], hv.y);
            }
        }
#pragma unroll
        for (int b = 0; b < 4; b++) {
            ulonglong2 v;
            v.x = acc[0][b];
            v.y = acc[1][b];
            *(ulonglong2*)&ZP[b * ZP_BP + kc * ZP_KP + jp * 4] = v;
        }
        __syncthreads();   // bar 1: ZP ready

        // ---------------- reduce: all 384 threads, one (j,b) each ---------
        {
            const float* zp = &ZP[rb * ZP_BP + (rj >> 1) * 4 + (rj & 1) * 2];
            unsigned long long s2 = 0ull;
#pragma unroll
            for (int k2 = 0; k2 < 8; k2++)
                fadd2(s2, *(const unsigned long long*)(zp + k2 * ZP_KP));
            float lo, hi;
            unpack2(s2, lo, hi);
            ZF[rj * 4 + rb] = zxv + lo + hi;
        }
        if (tt + 1 < T_LEN) {
            const int tn = dir ? (t - 1) : (t + 1);
            zxv = __ldg(&zx[((size_t)tn * BATCH + bglob_r) * ZN + zcolr]);
        }
        __syncthreads();   // bar 2: ZF ready (post-dates ALL dot reads)

        // ---------------- cell + st.async push (no fences) ----------------
        if (tid < 128) {
            const int m = tid >> 2;
            const int b = tid & 3;
            const int w = tid >> 5;
            const int lane = tid & 31;
            float iv = ZF[m * 4 + b];
            float jv = ZF[(32 + m) * 4 + b];
            float ov = ZF[(64 + m) * 4 + b];
            float ig = sigm(iv);
            creg = (1.f - ig) * creg + ig * tanhf(jv);
            float nh = tanhf(creg) * sigm(ov);

            SH[b * 40 + m] = nh;
            __syncwarp();
            if ((tt + 1 < T_LEN) && lane < 8) {
                // lane pushes this warp's 8 float4 to rank==lane with
                // complete_tx on that rank's mbarrier (data = completion).
                // dest col = rank*32 + base lives in kc-chunk == rank.
                const unsigned hbm  = smaddr(&HS[(tt + 1) & 1][0]) + pdel;
                const unsigned rmb  = hmb_a + pdel;
#pragma unroll
                for (int pb = 0; pb < 4; pb++) {
#pragma unroll
                    for (int half = 0; half < 2; half++) {
                        const int base = w * 8 + half * 4;
                        float4 v = *(const float4*)&SH[pb * 40 + base];
                        st_async_f128(hbm + (pb * HS_BP + (int)rank * HS_KP + base) * 4, rmb, v);
                    }
                }
            }

            const int col = (int)rank * 32 + m;
            const int bglob = bg * 4 + b;
            y[((size_t)t * BATCH + bglob) * 512 + dir * 256 + col] = nh;
            if (tt == T_LEN - 1) {
                int si = 2 * layer + dir;
                hn[(size_t)si * (BATCH * 256) + bglob * 256 + col] = nh;
                cn[(size_t)si * (BATCH * 256) + bglob * 256 + col] = creg;
            }
        }
        // non-cell warps proceed straight to next step's wait
    }
}

// ------------------------- highway elementwise -----------------------------
__global__ __launch_bounds__(256) void highway_ew(
    const float4* __restrict__ gz, const float4* __restrict__ raw,
    const float4* __restrict__ prev, float4* __restrict__ dst, int n4)
{
    int i = blockIdx.x * blockDim.x + threadIdx.x;
    if (i < n4) {
        float4 G = gz[i], R = raw[i], P = prev[i], o;
        float s;
        s = sigm(G.x); o.x = s * R.x + (1.f - s) * P.x;
        s = sigm(G.y); o.y = s * R.y + (1.f - s) * P.y;
        s = sigm(G.z); o.z = s * R.z + (1.f - s) * P.z;
        s = sigm(G.w); o.w = s * R.w + (1.f - s) * P.w;
        dst[i] = o;
    }
}

// ------------------------- host launcher -----------------------------------
extern "C" void kernel_launch(void* const* d_in, const int* in_sizes, int n_in,
                              void* d_out, int out_size)
{
    (void)in_sizes; (void)n_in; (void)out_size;

    const float* x    = (const float*)d_in[0];
    const float* h0   = (const float*)d_in[1];
    const float* c0   = (const float*)d_in[2];
    const float* Wf0  = (const float*)d_in[3];
    const float* bf0  = (const float*)d_in[4];
    const float* Wb0  = (const float*)d_in[5];
    const float* bb0  = (const float*)d_in[6];
    const float* Wf1  = (const float*)d_in[7];
    const float* bf1  = (const float*)d_in[8];
    const float* Wb1  = (const float*)d_in[9];
    const float* bb1  = (const float*)d_in[10];
    const float* Wf2  = (const float*)d_in[11];
    const float* bf2  = (const float*)d_in[12];
    const float* Wb2  = (const float*)d_in[13];
    const float* bb2  = (const float*)d_in[14];
    const float* W_hw = (const float*)d_in[15];
    const float* b_hw = (const float*)d_in[16];

    float* out = (float*)d_out;
    float* hn  = out + (size_t)MROWS * 512;
    float* cn  = hn + 6 * BATCH * 256;

    float *zxf, *zxb, *buf0, *buf1;
    cudaGetSymbolAddress((void**)&zxf,  g_zxf);
    cudaGetSymbolAddress((void**)&zxb,  g_zxb);
    cudaGetSymbolAddress((void**)&buf0, g_buf0);
    cudaGetSymbolAddress((void**)&buf1, g_buf1);

    const dim3 g768(ZN / BN, MROWS / BM);   // (6, 256)
    const dim3 g512(512 / BN, MROWS / BM);  // (4, 256)
    const int n4 = (MROWS * 512) / 4;
    const int ewb = (n4 + 255) / 256;

    // ---- layer 0 ----
    sgemm_bias<<<g768, 256>>>(x, Wf0, bf0, zxf, MROWS, ZN, 256);
    sgemm_bias<<<g768, 256>>>(x, Wb0, bb0, zxb, MROWS, ZN, 256);
    recur14<<<128, 384>>>(Wf0 + (size_t)256 * ZN, Wb0 + (size_t)256 * ZN,
                          h0, c0, buf0, hn, cn, 0);
    // ---- layer 1 ----
    sgemm_bias<<<g768, 256>>>(buf0, Wf1, bf1, zxf, MROWS, ZN, 512);
    sgemm_bias<<<g768, 256>>>(buf0, Wb1, bb1, zxb, MROWS, ZN, 512);
    recur14<<<128, 384>>>(Wf1 + (size_t)512 * ZN, Wb1 + (size_t)512 * ZN,
                          h0, c0, buf1, hn, cn, 1);
    sgemm_bias<<<g512, 256>>>(buf1, W_hw, b_hw, zxf, MROWS, 512, 512);
    highway_ew<<<ewb, 256>>>((const float4*)zxf, (const float4*)buf1,
                             (const float4*)buf0, (float4*)buf1, n4);
    // ---- layer 2 ----
    sgemm_bias<<<g768, 256>>>(buf1, Wf2, bf2, zxf, MROWS, ZN, 512);
    sgemm_bias<<<g768, 256>>>(buf1, Wb2, bb2, zxb, MROWS, ZN, 512);
    recur14<<<128, 384>>>(Wf2 + (size_t)512 * ZN, Wb2 + (size_t)512 * ZN,
                          h0, c0, buf0, hn, cn, 2);
    sgemm_bias<<<g512, 256>>>(buf0, W_hw, b_hw, zxf, MROWS, 512, 512);
    highway_ew<<<ewb, 256>>>((const float4*)zxf, (const float4*)buf0,
                             (const float4*)buf1, (float4*)out, n4);
}

// round 16
// speedup vs baseline: 1.0591x; 1.0591x over previous
#include <cuda_runtime.h>
#include <cstdint>
#include <cstddef>

// ---------------------------------------------------------------------------
// BiLSTM T=1024 B=32 H=256 L=3, 3-gate cell, highway on l>0.
//   zx GEMMs: FFMA2 SGEMM BM128xBN128, 2-stage pipeline, 1 barrier/tile.
//   recurrence: 16 clusters x 8 CTAs (dir x 4-batch group). Wh in registers.
//   h exchange: st.async DSMEM stores with mbarrier complete_tx (R13-proven).
//   R16: k-paired FFMA2 dot with q-outer schedule — all 8 accumulators
//   active per q (reuse distance 8 insts >> lat 4); zero packs in hot loop.
// ---------------------------------------------------------------------------

#define T_LEN 1024
#define BATCH 32
#define ZN    768
#define MROWS (T_LEN*BATCH)
#define H_BYTES_PER_STEP 4096   // 256 cols x 4 batches x 4B into each CTA

__device__ float g_zxf[(size_t)MROWS * ZN];
__device__ float g_zxb[(size_t)MROWS * ZN];
__device__ float g_buf0[(size_t)MROWS * 512];
__device__ float g_buf1[(size_t)MROWS * 512];

__device__ __forceinline__ float sigm(float x) { return 1.f / (1.f + __expf(-x)); }

__device__ __forceinline__ unsigned long long pack2(float lo, float hi) {
    unsigned long long r;
    asm("mov.b64 %0, {%1, %2};" : "=l"(r) : "f"(lo), "f"(hi));
    return r;
}
__device__ __forceinline__ void unpack2(unsigned long long v, float& lo, float& hi) {
    asm("mov.b64 {%0, %1}, %2;" : "=f"(lo), "=f"(hi) : "l"(v));
}
__device__ __forceinline__ void ffma2(unsigned long long& d, unsigned long long a, unsigned long long b) {
    asm("fma.rn.f32x2 %0, %1, %2, %3;" : "=l"(d) : "l"(a), "l"(b), "l"(d));
}
__device__ __forceinline__ void fadd2(unsigned long long& d, unsigned long long a) {
    asm("add.rn.f32x2 %0, %1, %2;" : "=l"(d) : "l"(d), "l"(a));
}
__device__ __forceinline__ unsigned smaddr(const void* p) {
    unsigned a;
    asm("{ .reg .u64 t; cvta.to.shared.u64 t, %1; cvt.u32.u64 %0, t; }" : "=r"(a) : "l"(p));
    return a;
}
__device__ __forceinline__ unsigned mapa_addr(unsigned addr, unsigned rank) {
    unsigned ra;
    asm("mapa.shared::cluster.u32 %0, %1, %2;" : "=r"(ra) : "r"(addr), "r"(rank));
    return ra;
}
// Async DSMEM store: data + 16 tx-bytes delivered to the destination CTA's
// mbarrier. Both addresses live in the SAME destination CTA.
__device__ __forceinline__ void st_async_f128(unsigned raddr, unsigned rmbar, float4 v) {
    asm volatile("st.async.shared::cluster.mbarrier::complete_tx::bytes.v4.f32 "
                 "[%0], {%1,%2,%3,%4}, [%5];"
                 :: "r"(raddr), "f"(v.x), "f"(v.y), "f"(v.z), "f"(v.w), "r"(rmbar)
                 : "memory");
}
__device__ __forceinline__ void mbar_init(unsigned addr, unsigned cnt) {
    asm volatile("mbarrier.init.shared.b64 [%0], %1;" :: "r"(addr), "r"(cnt) : "memory");
}
__device__ __forceinline__ void mbar_expect_tx(unsigned addr, unsigned bytes) {
    asm volatile("mbarrier.arrive.expect_tx.shared.b64 _, [%0], %1;"
                 :: "r"(addr), "r"(bytes) : "memory");
}
__device__ __forceinline__ void mbar_wait(unsigned addr, unsigned parity) {
    unsigned done;
    asm volatile("{ .reg .pred p; "
                 "mbarrier.try_wait.parity.acquire.cta.shared::cta.b64 p, [%1], %2; "
                 "selp.b32 %0, 1, 0, p; }"
                 : "=r"(done) : "r"(addr), "r"(parity) : "memory");
    if (!done) {
        asm volatile("{ .reg .pred P1; "
                     "WL_%=: mbarrier.try_wait.parity.acquire.cta.shared::cta.b64 P1, [%0], %1, 0x989680; "
                     "@P1 bra.uni WD_%=; bra.uni WL_%=; WD_%=: }"
                     :: "r"(addr), "r"(parity) : "memory");
    }
}
#define CLUSTER_SYNC() do { \
    asm volatile("barrier.cluster.arrive.aligned;" ::: "memory"); \
    asm volatile("barrier.cluster.wait.aligned;" ::: "memory"); \
} while (0)

// ------------------------- SGEMM (FFMA2, BM128 x BN128, 1 bar/tile) --------
#define BM 128
#define BN 128
#define BK 16

__global__ __launch_bounds__(256, 2) void sgemm_bias(
    const float* __restrict__ A, const float* __restrict__ B,
    const float* __restrict__ bias, float* __restrict__ C,
    int M, int N, int K)
{
    __shared__ float As[2][BK][BM];
    __shared__ float Bs[2][BK][BN];

    const int bm = blockIdx.y * BM;
    const int bn = blockIdx.x * BN;
    const int tid = threadIdx.x;
    const int tx = tid & 15;
    const int ty = tid >> 4;

    const int ar0 = tid >> 2;
    const int ac4 = tid & 3;
    const int brow = tid >> 4;
    const int bc = tid & 15;

    unsigned long long acc2[4][8];
#pragma unroll
    for (int p = 0; p < 4; p++)
#pragma unroll
        for (int j = 0; j < 8; j++) acc2[p][j] = 0ull;

    const int nIter = K >> 4;

    float4 a0, a1, b0, b1;
    a0 = *(const float4*)(A + (size_t)(bm + ar0) * K + ac4 * 4);
    a1 = *(const float4*)(A + (size_t)(bm + 64 + ar0) * K + ac4 * 4);
    b0 = *(const float4*)(B + (size_t)brow * N + bn + bc * 4);
    b1 = *(const float4*)(B + (size_t)brow * N + bn + 64 + bc * 4);

    for (int it = 0; it < nIter; it++) {
        const int s = it & 1;
        As[s][ac4 * 4 + 0][ar0] = a0.x;
        As[s][ac4 * 4 + 1][ar0] = a0.y;
        As[s][ac4 * 4 + 2][ar0] = a0.z;
        As[s][ac4 * 4 + 3][ar0] = a0.w;
        As[s][ac4 * 4 + 0][64 + ar0] = a1.x;
        As[s][ac4 * 4 + 1][64 + ar0] = a1.y;
        As[s][ac4 * 4 + 2][64 + ar0] = a1.z;
        As[s][ac4 * 4 + 3][64 + ar0] = a1.w;
        *(float4*)&Bs[s][brow][bc * 4]      = b0;
        *(float4*)&Bs[s][brow][64 + bc * 4] = b1;
        __syncthreads();
        if (it + 1 < nIter) {
            int k0 = (it + 1) * BK;
            a0 = *(const float4*)(A + (size_t)(bm + ar0) * K + k0 + ac4 * 4);
            a1 = *(const float4*)(A + (size_t)(bm + 64 + ar0) * K + k0 + ac4 * 4);
            b0 = *(const float4*)(B + (size_t)(k0 + brow) * N + bn + bc * 4);
            b1 = *(const float4*)(B + (size_t)(k0 + brow) * N + bn + 64 + bc * 4);
        }
#pragma unroll
        for (int k = 0; k < BK; k++) {
            ulonglong2 A0 = *(const ulonglong2*)&As[s][k][ty * 8];
            ulonglong2 A1 = *(const ulonglong2*)&As[s][k][ty * 8 + 4];
            float4 bv0 = *(const float4*)&Bs[s][k][tx * 4];
            float4 bv1 = *(const float4*)&Bs[s][k][64 + tx * 4];
            unsigned long long bb;
#define NCOL(J, V)                                                     \
            bb = pack2(V, V);                                          \
            ffma2(acc2[0][J], A0.x, bb); ffma2(acc2[1][J], A0.y, bb);  \
            ffma2(acc2[2][J], A1.x, bb); ffma2(acc2[3][J], A1.y, bb);
            NCOL(0, bv0.x) NCOL(1, bv0.y) NCOL(2, bv0.z) NCOL(3, bv0.w)
            NCOL(4, bv1.x) NCOL(5, bv1.y) NCOL(6, bv1.z) NCOL(7, bv1.w)
#undef NCOL
        }
    }
    float4 bbA = *(const float4*)(bias + bn + tx * 4);
    float4 bbB = *(const float4*)(bias + bn + 64 + tx * 4);
#pragma unroll
    for (int p = 0; p < 4; p++) {
        float lo[8], hi[8];
#pragma unroll
        for (int j = 0; j < 8; j++) unpack2(acc2[p][j], lo[j], hi[j]);
        int row0 = bm + ty * 8 + 2 * p;
        float4 o;
        o.x = lo[0] + bbA.x; o.y = lo[1] + bbA.y; o.z = lo[2] + bbA.z; o.w = lo[3] + bbA.w;
        *(float4*)(C + (size_t)row0 * N + bn + tx * 4) = o;
        o.x = lo[4] + bbB.x; o.y = lo[5] + bbB.y; o.z = lo[6] + bbB.z; o.w = lo[7] + bbB.w;
        *(float4*)(C + (size_t)row0 * N + bn + 64 + tx * 4) = o;
        o.x = hi[0] + bbA.x; o.y = hi[1] + bbA.y; o.z = hi[2] + bbA.z; o.w = hi[3] + bbA.w;
        *(float4*)(C + (size_t)(row0 + 1) * N + bn + tx * 4) = o;
        o.x = hi[4] + bbB.x; o.y = hi[5] + bbB.y; o.z = hi[6] + bbB.z; o.w = hi[7] + bbB.w;
        *(float4*)(C + (size_t)(row0 + 1) * N + bn + 64 + tx * 4) = o;
    }
}

// ------------------------- recurrent scan ----------------------------------
// 128 CTAs, cluster 8. cid = blockIdx.x/8; dir = cid>>3; bg = cid&7.
// CTA rank r owns h-cols [r*32, r*32+32) -> 96 z-cols x 4 batches. 384 thr.
// R16 dot: thread = (jp = tid%48 [j-pair], kc = tid/48 [32-k chunk]).
//   W regs: 32 ull of k-pairs. Per q: load hv for all 4 b (4 LDS.128), then
//   8 FFMA2 on .x across all 8 accs, then 8 on .y -> reuse distance 8.
// ZP: [b][kc][jp] (pitch 192/kc, 1544/b: rb-groups on distinct bank sets).
// Sync: st.async + complete_tx mbarrier (R13-proven, no fences).
#define HS_KP 48
#define HS_BP 384
#define ZP_KP 192
#define ZP_BP 1544

__global__ void __cluster_dims__(8, 1, 1) __launch_bounds__(384, 1)
recur16(const float* __restrict__ Whf, const float* __restrict__ Whb,
        const float* __restrict__ h0, const float* __restrict__ c0,
        float* __restrict__ y, float* __restrict__ hn, float* __restrict__ cn,
        int layer)
{
    __shared__ __align__(16) float HS[2][4 * HS_BP]; // h pingpong [b][kc][k]
    __shared__ __align__(16) float ZP[4 * ZP_BP];    // dot partials (ull each)
    __shared__ float ZF[96 * 4];                     // reduced gate sums
    __shared__ __align__(16) float SH[4 * 40];       // nh staging
    __shared__ unsigned long long hmb;               // mbarrier (count 1 + tx)

    const int cid = blockIdx.x >> 3;
    const int dir = cid >> 3;
    const int bg  = cid & 7;
    unsigned rank;
    asm("mov.u32 %0, %%cluster_ctarank;" : "=r"(rank));

    const float* Wh = dir ? Whb : Whf;
    const float* zx = dir ? g_zxb : g_zxf;
    const int tid = threadIdx.x;
    const unsigned hmb_a = smaddr(&hmb);

    const int jp = tid % 48;          // j-pair id (2 j's within one gate)
    const int kc = tid / 48;          // 0..7, k chunk [kc*32, kc*32+32)
    const int rj = tid >> 2;          // reduce: z-col 0..95
    const int rb = tid & 3;
    const int bglob_r = bg * 4 + rb;
    const int zcolr = (rj >> 5) * 256 + (int)rank * 32 + (rj & 31);

    // per-thread DSMEM delta for its push target (rank = lane&7)
    const unsigned anchor = smaddr(&HS[0][0]);
    const unsigned pdel = mapa_addr(anchor, (unsigned)(tid & 7)) - anchor;

    // ---- W slice into registers: k-pairs for 2 j's ----
    const int gate = jp >> 4;                              // 0..2
    const int zc0 = gate * 256 + (int)rank * 32 + (jp & 15) * 2;  // j0 col
    unsigned long long wA[16], wB[16];
#pragma unroll
    for (int kk = 0; kk < 16; kk++) {
        const float* w0 = Wh + (size_t)(kc * 32 + kk * 2) * ZN;
        const float* w1 = w0 + ZN;
        wA[kk] = pack2(__ldg(w0 + zc0),     __ldg(w1 + zc0));      // j0: (k0,k1)
        wB[kk] = pack2(__ldg(w0 + zc0 + 1), __ldg(w1 + zc0 + 1));  // j1
    }

    // ---- init h buffer 0, c, mbarrier ----
    for (int it = tid; it < 4 * 256; it += 384) {
        int b = it >> 8, k = it & 255;
        HS[0][b * HS_BP + (k >> 5) * HS_KP + (k & 31)] = h0[k];
    }
    float creg = 0.f;
    if (tid < 128) creg = c0[(int)rank * 32 + (tid >> 2)];
    if (tid == 0) mbar_init(hmb_a, 1);
    __syncthreads();
    CLUSTER_SYNC();   // inits + HS[0] visible cluster-wide before any st.async

    const int t0 = dir ? (T_LEN - 1) : 0;
    float zxv = __ldg(&zx[((size_t)t0 * BATCH + bglob_r) * ZN + zcolr]);

    for (int tt = 0; tt < T_LEN; tt++) {
        const int t = dir ? (T_LEN - 1 - tt) : tt;

        if (tt) mbar_wait(hmb_a, (tt & 1) ^ 1);   // h[tt&1] fully arrived
        if (tid == 0 && tt + 1 < T_LEN) mbar_expect_tx(hmb_a, H_BYTES_PER_STEP);

        // -------- dot: k-paired FFMA2, q-outer, 8 live accumulators -------
        const float* hb0 = &HS[tt & 1][kc * HS_KP];
        const ulonglong2* hp0 = (const ulonglong2*)(hb0 + 0 * HS_BP);
        const ulonglong2* hp1 = (const ulonglong2*)(hb0 + 1 * HS_BP);
        const ulonglong2* hp2 = (const ulonglong2*)(hb0 + 2 * HS_BP);
        const ulonglong2* hp3 = (const ulonglong2*)(hb0 + 3 * HS_BP);
        unsigned long long acc[2][4];
#pragma unroll
        for (int g2 = 0; g2 < 2; g2++)
#pragma unroll
            for (int b = 0; b < 4; b++) acc[g2][b] = 0ull;

#pragma unroll
        for (int q = 0; q < 8; q++) {
            ulonglong2 hv0 = hp0[q];
            ulonglong2 hv1 = hp1[q];
            ulonglong2 hv2 = hp2[q];
            ulonglong2 hv3 = hp3[q];
            // .x batch: 8 independent FFMA2 (one per accumulator)
            ffma2(acc[0][0], wA[2 * q], hv0.x); ffma2(acc[1][0], wB[2 * q], hv0.x);
            ffma2(acc[0][1], wA[2 * q], hv1.x); ffma2(acc[1][1], wB[2 * q], hv1.x);
            ffma2(acc[0][2], wA[2 * q], hv2.x); ffma2(acc[1][2], wB[2 * q], hv2.x);
            ffma2(acc[0][3], wA[2 * q], hv3.x); ffma2(acc[1][3], wB[2 * q], hv3.x);
            // .y batch: reuse distance 8 insts (~16 cyc) >> lat 4
            ffma2(acc[0][0], wA[2 * q + 1], hv0.y); ffma2(acc[1][0], wB[2 * q + 1], hv0.y);
            ffma2(acc[0][1], wA[2 * q + 1], hv1.y); ffma2(acc[1][1], wB[2 * q + 1], hv1.y);
            ffma2(acc[0][2], wA[2 * q + 1], hv2.y); ffma2(acc[1][2], wB[2 * q + 1], hv2.y);
            ffma2(acc[0][3], wA[2 * q + 1], hv3.y); ffma2(acc[1][3], wB[2 * q + 1], hv3.y);
        }
#pragma unroll
        for (int b = 0; b < 4; b++) {
            ulonglong2 v;
            v.x = acc[0][b];
            v.y = acc[1][b];
            *(ulonglong2*)&ZP[b * ZP_BP + kc * ZP_KP + jp * 4] = v;
        }
        __syncthreads();   // bar 1: ZP ready

        // ---------------- reduce: all 384 threads, one (j,b) each ---------
        {
            const float* zp = &ZP[rb * ZP_BP + (rj >> 1) * 4 + (rj & 1) * 2];
            unsigned long long s2 = 0ull;
#pragma unroll
            for (int k2 = 0; k2 < 8; k2++)
                fadd2(s2, *(const unsigned long long*)(zp + k2 * ZP_KP));
            float lo, hi;
            unpack2(s2, lo, hi);
            ZF[rj * 4 + rb] = zxv + lo + hi;
        }
        if (tt + 1 < T_LEN) {
            const int tn = dir ? (t - 1) : (t + 1);
            zxv = __ldg(&zx[((size_t)tn * BATCH + bglob_r) * ZN + zcolr]);
        }
        __syncthreads();   // bar 2: ZF ready (post-dates ALL dot reads)

        // ---------------- cell + st.async push (no fences) ----------------
        if (tid < 128) {
            const int m = tid >> 2;
            const int b = tid & 3;
            const int w = tid >> 5;
            const int lane = tid & 31;
            float iv = ZF[m * 4 + b];
            float jv = ZF[(32 + m) * 4 + b];
            float ov = ZF[(64 + m) * 4 + b];
            float ig = sigm(iv);
            creg = (1.f - ig) * creg + ig * tanhf(jv);
            float nh = tanhf(creg) * sigm(ov);

            SH[b * 40 + m] = nh;
            __syncwarp();
            if ((tt + 1 < T_LEN) && lane < 8) {
                // lane pushes this warp's 8 float4 to rank==lane with
                // complete_tx on that rank's mbarrier (data = completion).
                const unsigned hbm  = smaddr(&HS[(tt + 1) & 1][0]) + pdel;
                const unsigned rmb  = hmb_a + pdel;
#pragma unroll
                for (int pb = 0; pb < 4; pb++) {
#pragma unroll
                    for (int half = 0; half < 2; half++) {
                        const int base = w * 8 + half * 4;
                        float4 v = *(const float4*)&SH[pb * 40 + base];
                        st_async_f128(hbm + (pb * HS_BP + (int)rank * HS_KP + base) * 4, rmb, v);
                    }
                }
            }

            const int col = (int)rank * 32 + m;
            const int bglob = bg * 4 + b;
            y[((size_t)t * BATCH + bglob) * 512 + dir * 256 + col] = nh;
            if (tt == T_LEN - 1) {
                int si = 2 * layer + dir;
                hn[(size_t)si * (BATCH * 256) + bglob * 256 + col] = nh;
                cn[(size_t)si * (BATCH * 256) + bglob * 256 + col] = creg;
            }
        }
        // non-cell warps proceed straight to next step's wait
    }
}

// ------------------------- highway elementwise -----------------------------
__global__ __launch_bounds__(256) void highway_ew(
    const float4* __restrict__ gz, const float4* __restrict__ raw,
    const float4* __restrict__ prev, float4* __restrict__ dst, int n4)
{
    int i = blockIdx.x * blockDim.x + threadIdx.x;
    if (i < n4) {
        float4 G = gz[i], R = raw[i], P = prev[i], o;
        float s;
        s = sigm(G.x); o.x = s * R.x + (1.f - s) * P.x;
        s = sigm(G.y); o.y = s * R.y + (1.f - s) * P.y;
        s = sigm(G.z); o.z = s * R.z + (1.f - s) * P.z;
        s = sigm(G.w); o.w = s * R.w + (1.f - s) * P.w;
        dst[i] = o;
    }
}

// ------------------------- host launcher -----------------------------------
extern "C" void kernel_launch(void* const* d_in, const int* in_sizes, int n_in,
                              void* d_out, int out_size)
{
    (void)in_sizes; (void)n_in; (void)out_size;

    const float* x    = (const float*)d_in[0];
    const float* h0   = (const float*)d_in[1];
    const float* c0   = (const float*)d_in[2];
    const float* Wf0  = (const float*)d_in[3];
    const float* bf0  = (const float*)d_in[4];
    const float* Wb0  = (const float*)d_in[5];
    const float* bb0  = (const float*)d_in[6];
    const float* Wf1  = (const float*)d_in[7];
    const float* bf1  = (const float*)d_in[8];
    const float* Wb1  = (const float*)d_in[9];
    const float* bb1  = (const float*)d_in[10];
    const float* Wf2  = (const float*)d_in[11];
    const float* bf2  = (const float*)d_in[12];
    const float* Wb2  = (const float*)d_in[13];
    const float* bb2  = (const float*)d_in[14];
    const float* W_hw = (const float*)d_in[15];
    const float* b_hw = (const float*)d_in[16];

    float* out = (float*)d_out;
    float* hn  = out + (size_t)MROWS * 512;
    float* cn  = hn + 6 * BATCH * 256;

    float *zxf, *zxb, *buf0, *buf1;
    cudaGetSymbolAddress((void**)&zxf,  g_zxf);
    cudaGetSymbolAddress((void**)&zxb,  g_zxb);
    cudaGetSymbolAddress((void**)&buf0, g_buf0);
    cudaGetSymbolAddress((void**)&buf1, g_buf1);

    const dim3 g768(ZN / BN, MROWS / BM);   // (6, 256)
    const dim3 g512(512 / BN, MROWS / BM);  // (4, 256)
    const int n4 = (MROWS * 512) / 4;
    const int ewb = (n4 + 255) / 256;

    // ---- layer 0 ----
    sgemm_bias<<<g768, 256>>>(x, Wf0, bf0, zxf, MROWS, ZN, 256);
    sgemm_bias<<<g768, 256>>>(x, Wb0, bb0, zxb, MROWS, ZN, 256);
    recur16<<<128, 384>>>(Wf0 + (size_t)256 * ZN, Wb0 + (size_t)256 * ZN,
                          h0, c0, buf0, hn, cn, 0);
    // ---- layer 1 ----
    sgemm_bias<<<g768, 256>>>(buf0, Wf1, bf1, zxf, MROWS, ZN, 512);
    sgemm_bias<<<g768, 256>>>(buf0, Wb1, bb1, zxb, MROWS, ZN, 512);
    recur16<<<128, 384>>>(Wf1 + (size_t)512 * ZN, Wb1 + (size_t)512 * ZN,
                          h0, c0, buf1, hn, cn, 1);
    sgemm_bias<<<g512, 256>>>(buf1, W_hw, b_hw, zxf, MROWS, 512, 512);
    highway_ew<<<ewb, 256>>>((const float4*)zxf, (const float4*)buf1,
                             (const float4*)buf0, (float4*)buf1, n4);
    // ---- layer 2 ----
    sgemm_bias<<<g768, 256>>>(buf1, Wf2, bf2, zxf, MROWS, ZN, 512);
    sgemm_bias<<<g768, 256>>>(buf1, Wb2, bb2, zxb, MROWS, ZN, 512);
    recur16<<<128, 384>>>(Wf2 + (size_t)512 * ZN, Wb2 + (size_t)512 * ZN,
                          h0, c0, buf0, hn, cn, 2);
    sgemm_bias<<<g512, 256>>>(buf0, W_hw, b_hw, zxf, MROWS, 512, 512);
    highway_ew<<<ewb, 256>>>((const float4*)zxf, (const float4*)buf0,
                             (const float4*)buf1, (float4*)out, n4);
}

// round 17
// speedup vs baseline: 1.2364x; 1.1674x over previous
#include <cuda_runtime.h>
#include <cstdint>
#include <cstddef>

// ---------------------------------------------------------------------------
// BiLSTM T=1024 B=32 H=256 L=3, 3-gate cell, highway on l>0.
//   zx GEMMs: FFMA2 SGEMM BM128xBN128, 2-stage pipeline, 1 barrier/tile.
//   recurrence R17: 32 clusters x 8 CTAs (dir x 16 batch-groups of 2),
//   grid 256 with __launch_bounds__(384,2) -> TWO co-resident CTAs per SM;
//   one chain's compute hides the other chain's sync latency. Per-CTA work
//   is halved (2 batches). Protocol = R13 st.async + complete_tx (proven).
// ---------------------------------------------------------------------------

#define T_LEN 1024
#define BATCH 32
#define ZN    768
#define MROWS (T_LEN*BATCH)
#define H_BYTES_PER_STEP 2048   // 256 cols x 2 batches x 4B into each CTA

__device__ float g_zxf[(size_t)MROWS * ZN];
__device__ float g_zxb[(size_t)MROWS * ZN];
__device__ float g_buf0[(size_t)MROWS * 512];
__device__ float g_buf1[(size_t)MROWS * 512];

__device__ __forceinline__ float sigm(float x) { return 1.f / (1.f + __expf(-x)); }

__device__ __forceinline__ unsigned long long pack2(float lo, float hi) {
    unsigned long long r;
    asm("mov.b64 %0, {%1, %2};" : "=l"(r) : "f"(lo), "f"(hi));
    return r;
}
__device__ __forceinline__ void unpack2(unsigned long long v, float& lo, float& hi) {
    asm("mov.b64 {%0, %1}, %2;" : "=f"(lo), "=f"(hi) : "l"(v));
}
__device__ __forceinline__ void ffma2(unsigned long long& d, unsigned long long a, unsigned long long b) {
    asm("fma.rn.f32x2 %0, %1, %2, %3;" : "=l"(d) : "l"(a), "l"(b), "l"(d));
}
__device__ __forceinline__ unsigned smaddr(const void* p) {
    unsigned a;
    asm("{ .reg .u64 t; cvta.to.shared.u64 t, %1; cvt.u32.u64 %0, t; }" : "=r"(a) : "l"(p));
    return a;
}
__device__ __forceinline__ unsigned mapa_addr(unsigned addr, unsigned rank) {
    unsigned ra;
    asm("mapa.shared::cluster.u32 %0, %1, %2;" : "=r"(ra) : "r"(addr), "r"(rank));
    return ra;
}
// Async DSMEM store: data + 16 tx-bytes delivered to the destination CTA's
// mbarrier. Both addresses live in the SAME destination CTA.
__device__ __forceinline__ void st_async_f128(unsigned raddr, unsigned rmbar, float4 v) {
    asm volatile("st.async.shared::cluster.mbarrier::complete_tx::bytes.v4.f32 "
                 "[%0], {%1,%2,%3,%4}, [%5];"
                 :: "r"(raddr), "f"(v.x), "f"(v.y), "f"(v.z), "f"(v.w), "r"(rmbar)
                 : "memory");
}
__device__ __forceinline__ void mbar_init(unsigned addr, unsigned cnt) {
    asm volatile("mbarrier.init.shared.b64 [%0], %1;" :: "r"(addr), "r"(cnt) : "memory");
}
__device__ __forceinline__ void mbar_expect_tx(unsigned addr, unsigned bytes) {
    asm volatile("mbarrier.arrive.expect_tx.shared.b64 _, [%0], %1;"
                 :: "r"(addr), "r"(bytes) : "memory");
}
__device__ __forceinline__ void mbar_wait(unsigned addr, unsigned parity) {
    unsigned done;
    asm volatile("{ .reg .pred p; "
                 "mbarrier.try_wait.parity.acquire.cta.shared::cta.b64 p, [%1], %2; "
                 "selp.b32 %0, 1, 0, p; }"
                 : "=r"(done) : "r"(addr), "r"(parity) : "memory");
    if (!done) {
        asm volatile("{ .reg .pred P1; "
                     "WL_%=: mbarrier.try_wait.parity.acquire.cta.shared::cta.b64 P1, [%0], %1, 0x989680; "
                     "@P1 bra.uni WD_%=; bra.uni WL_%=; WD_%=: }"
                     :: "r"(addr), "r"(parity) : "memory");
    }
}
#define CLUSTER_SYNC() do { \
    asm volatile("barrier.cluster.arrive.aligned;" ::: "memory"); \
    asm volatile("barrier.cluster.wait.aligned;" ::: "memory"); \
} while (0)

// ------------------------- SGEMM (FFMA2, BM128 x BN128, 1 bar/tile) --------
#define BM 128
#define BN 128
#define BK 16

__global__ __launch_bounds__(256, 2) void sgemm_bias(
    const float* __restrict__ A, const float* __restrict__ B,
    const float* __restrict__ bias, float* __restrict__ C,
    int M, int N, int K)
{
    __shared__ float As[2][BK][BM];
    __shared__ float Bs[2][BK][BN];

    const int bm = blockIdx.y * BM;
    const int bn = blockIdx.x * BN;
    const int tid = threadIdx.x;
    const int tx = tid & 15;
    const int ty = tid >> 4;

    const int ar0 = tid >> 2;
    const int ac4 = tid & 3;
    const int brow = tid >> 4;
    const int bc = tid & 15;

    unsigned long long acc2[4][8];
#pragma unroll
    for (int p = 0; p < 4; p++)
#pragma unroll
        for (int j = 0; j < 8; j++) acc2[p][j] = 0ull;

    const int nIter = K >> 4;

    float4 a0, a1, b0, b1;
    a0 = *(const float4*)(A + (size_t)(bm + ar0) * K + ac4 * 4);
    a1 = *(const float4*)(A + (size_t)(bm + 64 + ar0) * K + ac4 * 4);
    b0 = *(const float4*)(B + (size_t)brow * N + bn + bc * 4);
    b1 = *(const float4*)(B + (size_t)brow * N + bn + 64 + bc * 4);

    for (int it = 0; it < nIter; it++) {
        const int s = it & 1;
        As[s][ac4 * 4 + 0][ar0] = a0.x;
        As[s][ac4 * 4 + 1][ar0] = a0.y;
        As[s][ac4 * 4 + 2][ar0] = a0.z;
        As[s][ac4 * 4 + 3][ar0] = a0.w;
        As[s][ac4 * 4 + 0][64 + ar0] = a1.x;
        As[s][ac4 * 4 + 1][64 + ar0] = a1.y;
        As[s][ac4 * 4 + 2][64 + ar0] = a1.z;
        As[s][ac4 * 4 + 3][64 + ar0] = a1.w;
        *(float4*)&Bs[s][brow][bc * 4]      = b0;
        *(float4*)&Bs[s][brow][64 + bc * 4] = b1;
        __syncthreads();
        if (it + 1 < nIter) {
            int k0 = (it + 1) * BK;
            a0 = *(const float4*)(A + (size_t)(bm + ar0) * K + k0 + ac4 * 4);
            a1 = *(const float4*)(A + (size_t)(bm + 64 + ar0) * K + k0 + ac4 * 4);
            b0 = *(const float4*)(B + (size_t)(k0 + brow) * N + bn + bc * 4);
            b1 = *(const float4*)(B + (size_t)(k0 + brow) * N + bn + 64 + bc * 4);
        }
#pragma unroll
        for (int k = 0; k < BK; k++) {
            ulonglong2 A0 = *(const ulonglong2*)&As[s][k][ty * 8];
            ulonglong2 A1 = *(const ulonglong2*)&As[s][k][ty * 8 + 4];
            float4 bv0 = *(const float4*)&Bs[s][k][tx * 4];
            float4 bv1 = *(const float4*)&Bs[s][k][64 + tx * 4];
            unsigned long long bb;
#define NCOL(J, V)                                                     \
            bb = pack2(V, V);                                          \
            ffma2(acc2[0][J], A0.x, bb); ffma2(acc2[1][J], A0.y, bb);  \
            ffma2(acc2[2][J], A1.x, bb); ffma2(acc2[3][J], A1.y, bb);
            NCOL(0, bv0.x) NCOL(1, bv0.y) NCOL(2, bv0.z) NCOL(3, bv0.w)
            NCOL(4, bv1.x) NCOL(5, bv1.y) NCOL(6, bv1.z) NCOL(7, bv1.w)
#undef NCOL
        }
    }
    float4 bbA = *(const float4*)(bias + bn + tx * 4);
    float4 bbB = *(const float4*)(bias + bn + 64 + tx * 4);
#pragma unroll
    for (int p = 0; p < 4; p++) {
        float lo[8], hi[8];
#pragma unroll
        for (int j = 0; j < 8; j++) unpack2(acc2[p][j], lo[j], hi[j]);
        int row0 = bm + ty * 8 + 2 * p;
        float4 o;
        o.x = lo[0] + bbA.x; o.y = lo[1] + bbA.y; o.z = lo[2] + bbA.z; o.w = lo[3] + bbA.w;
        *(float4*)(C + (size_t)row0 * N + bn + tx * 4) = o;
        o.x = lo[4] + bbB.x; o.y = lo[5] + bbB.y; o.z = lo[6] + bbB.z; o.w = lo[7] + bbB.w;
        *(float4*)(C + (size_t)row0 * N + bn + 64 + tx * 4) = o;
        o.x = hi[0] + bbA.x; o.y = hi[1] + bbA.y; o.z = hi[2] + bbA.z; o.w = hi[3] + bbA.w;
        *(float4*)(C + (size_t)(row0 + 1) * N + bn + tx * 4) = o;
        o.x = hi[4] + bbB.x; o.y = hi[5] + bbB.y; o.z = hi[6] + bbB.z; o.w = hi[7] + bbB.w;
        *(float4*)(C + (size_t)(row0 + 1) * N + bn + 64 + tx * 4) = o;
    }
}

// ------------------------- recurrent scan (2 batches/CTA, occ 2) -----------
// grid 256, cluster 8. cid = blockIdx.x/8; dir = cid>>4; bg = cid&15.
// CTA rank r owns h-cols [r*32, r*32+32) -> 96 z-cols x 2 batches. 384 thr,
// __launch_bounds__(384,2): two CTAs (independent scan chains) per SM.
// Dot: (jg = tid%24, kc = tid/24), W in regs (32 ull), acc[2][2].
// Partials ZP[b][kc][j] (pitch 104/kc, 1680/b: rb banks disjoint).
// Reduce: tid<192, one (j,b) each. Cell: tid<64 (m=tid>>1, b=tid&1).
// Sync: st.async + complete_tx mbarrier (R13-proven, no fences).
#define ZP_KP 104
#define ZP_BP 1680

__global__ void __cluster_dims__(8, 1, 1) __launch_bounds__(384, 2)
recur17(const float* __restrict__ Whf, const float* __restrict__ Whb,
        const float* __restrict__ h0, const float* __restrict__ c0,
        float* __restrict__ y, float* __restrict__ hn, float* __restrict__ cn,
        int layer)
{
    __shared__ __align__(16) float HS[2][2 * 264];   // h pingpong [b][k] pitch 264
    __shared__ __align__(16) float ZP[2 * ZP_BP];    // dot partials
    __shared__ float ZF[96 * 2];                     // reduced gate sums
    __shared__ __align__(16) float SH[2 * 40];       // nh staging
    __shared__ unsigned long long hmb;               // mbarrier (count 1 + tx)

    const int cid = blockIdx.x >> 3;
    const int dir = cid >> 4;
    const int bg  = cid & 15;
    unsigned rank;
    asm("mov.u32 %0, %%cluster_ctarank;" : "=r"(rank));

    const float* Wh = dir ? Whb : Whf;
    const float* zx = dir ? g_zxb : g_zxf;
    const int tid = threadIdx.x;
    const unsigned hmb_a = smaddr(&hmb);

    const int jg = tid % 24;
    const int kc = tid / 24;
    const int rj = tid >> 1;           // reduce: z-col (tid<192)
    const int rb = tid & 1;
    const int bglob_r = bg * 2 + rb;
    const int zcolr = (rj >> 5) * 256 + (int)rank * 32 + (rj & 31);

    // per-thread DSMEM delta for its push target (rank = lane&7)
    const unsigned anchor = smaddr(&HS[0][0]);
    const unsigned pdel = mapa_addr(anchor, (unsigned)(tid & 7)) - anchor;

    // ---- W slice into registers (j-quad x 16 k) ----
    const int gate = jg >> 3;
    const int colb = (int)rank * 32 + (jg & 7) * 4;
    const int zc0 = gate * 256 + colb;
    unsigned long long wA[16], wB[16];
#pragma unroll
    for (int kl = 0; kl < 16; kl++) {
        const float* wrow = Wh + (size_t)(kc * 16 + kl) * ZN + zc0;
        wA[kl] = pack2(__ldg(wrow + 0), __ldg(wrow + 1));
        wB[kl] = pack2(__ldg(wrow + 2), __ldg(wrow + 3));
    }

    // ---- init h buffer 0, c, mbarrier ----
    for (int it = tid; it < 2 * 256; it += 384) {
        int b = it >> 8, k = it & 255;
        HS[0][b * 264 + k] = h0[k];
    }
    float creg = 0.f;
    if (tid < 64) creg = c0[(int)rank * 32 + (tid >> 1)];
    if (tid == 0) mbar_init(hmb_a, 1);
    __syncthreads();
    CLUSTER_SYNC();   // inits + HS[0] visible cluster-wide before any st.async

    const int t0 = dir ? (T_LEN - 1) : 0;
    float zxv = 0.f;
    if (tid < 192)
        zxv = __ldg(&zx[((size_t)t0 * BATCH + bglob_r) * ZN + zcolr]);

    for (int tt = 0; tt < T_LEN; tt++) {
        const int t = dir ? (T_LEN - 1 - tt) : tt;

        if (tt) mbar_wait(hmb_a, (tt & 1) ^ 1);   // h[tt&1] fully arrived
        if (tid == 0 && tt + 1 < T_LEN) mbar_expect_tx(hmb_a, H_BYTES_PER_STEP);

        // ---------------- dot (W in regs, h broadcast from SMEM) ----------
        const float* hc = &HS[tt & 1][kc * 16];
        unsigned long long acc[2][2];
#pragma unroll
        for (int g2 = 0; g2 < 2; g2++)
#pragma unroll
            for (int b = 0; b < 2; b++) acc[g2][b] = 0ull;

#pragma unroll
        for (int q = 0; q < 4; q++) {
            float4 h0q = *(const float4*)(hc + 0 * 264 + q * 4);
            float4 h1q = *(const float4*)(hc + 1 * 264 + q * 4);
#define RSTEP(C, KL)                                                   \
            {                                                          \
                unsigned long long p;                                  \
                p = pack2(h0q.C, h0q.C);                               \
                ffma2(acc[0][0], wA[KL], p); ffma2(acc[1][0], wB[KL], p); \
                p = pack2(h1q.C, h1q.C);                               \
                ffma2(acc[0][1], wA[KL], p); ffma2(acc[1][1], wB[KL], p); \
            }
            RSTEP(x, (q * 4 + 0)) RSTEP(y, (q * 4 + 1))
            RSTEP(z, (q * 4 + 2)) RSTEP(w, (q * 4 + 3))
#undef RSTEP
        }
#pragma unroll
        for (int b = 0; b < 2; b++) {
            ulonglong2 v;
            v.x = acc[0][b];
            v.y = acc[1][b];
            *(ulonglong2*)&ZP[b * ZP_BP + kc * ZP_KP + jg * 4] = v;
        }
        __syncthreads();   // bar 1: ZP ready

        // ---------------- reduce: tid<192, one (j,b) each -----------------
        if (tid < 192) {
            float s = zxv;
            const float* zp = &ZP[rb * ZP_BP + rj];
#pragma unroll
            for (int k2 = 0; k2 < 16; k2++) s += zp[k2 * ZP_KP];
            ZF[rj * 2 + rb] = s;
            if (tt + 1 < T_LEN) {
                const int tn = dir ? (t - 1) : (t + 1);
                zxv = __ldg(&zx[((size_t)tn * BATCH + bglob_r) * ZN + zcolr]);
            }
        }
        __syncthreads();   // bar 2: ZF ready (post-dates ALL dot reads)

        // ---------------- cell + st.async push (no fences) ----------------
        if (tid < 64) {
            const int m = tid >> 1;
            const int b = tid & 1;
            const int w = tid >> 5;           // 0..1
            const int lane = tid & 31;
            float iv = ZF[m * 2 + b];
            float jv = ZF[(32 + m) * 2 + b];
            float ov = ZF[(64 + m) * 2 + b];
            float ig = sigm(iv);
            creg = (1.f - ig) * creg + ig * tanhf(jv);
            float nh = tanhf(creg) * sigm(ov);

            SH[b * 40 + m] = nh;
            __syncwarp();
            if ((tt + 1 < T_LEN) && lane < 8) {
                // lane pushes this warp's 16 cols x 2 batches (4 float4) to
                // rank==lane with complete_tx on that rank's mbarrier.
                const unsigned hbm = smaddr(&HS[(tt + 1) & 1][0]) + pdel;
                const unsigned rmb = hmb_a + pdel;
#pragma unroll
                for (int pb = 0; pb < 2; pb++) {
#pragma unroll
                    for (int half = 0; half < 2; half++) {
                        const int base = w * 16 + half * 4 + (half >> 1);
                        const int bb = w * 16 + half * 4;
                        float4 v = *(const float4*)&SH[pb * 40 + bb];
                        (void)base;
                        st_async_f128(hbm + (pb * 264 + (int)rank * 32 + bb) * 4, rmb, v);
                    }
                }
                // remaining 8 cols of this warp's 16-col half: halves 2..3
#pragma unroll
                for (int pb = 0; pb < 2; pb++) {
#pragma unroll
                    for (int half = 2; half < 4; half++) {
                        const int bb = w * 16 + half * 4;
                        float4 v = *(const float4*)&SH[pb * 40 + bb];
                        st_async_f128(hbm + (pb * 264 + (int)rank * 32 + bb) * 4, rmb, v);
                    }
                }
            }

            const int col = (int)rank * 32 + m;
            const int bglob = bg * 2 + b;
            y[((size_t)t * BATCH + bglob) * 512 + dir * 256 + col] = nh;
            if (tt == T_LEN - 1) {
                int si = 2 * layer + dir;
                hn[(size_t)si * (BATCH * 256) + bglob * 256 + col] = nh;
                cn[(size_t)si * (BATCH * 256) + bglob * 256 + col] = creg;
            }
        }
        // non-cell warps proceed straight to next step's wait
    }
}

// ------------------------- highway elementwise -----------------------------
__global__ __launch_bounds__(256) void highway_ew(
    const float4* __restrict__ gz, const float4* __restrict__ raw,
    const float4* __restrict__ prev, float4* __restrict__ dst, int n4)
{
    int i = blockIdx.x * blockDim.x + threadIdx.x;
    if (i < n4) {
        float4 G = gz[i], R = raw[i], P = prev[i], o;
        float s;
        s = sigm(G.x); o.x = s * R.x + (1.f - s) * P.x;
        s = sigm(G.y); o.y = s * R.y + (1.f - s) * P.y;
        s = sigm(G.z); o.z = s * R.z + (1.f - s) * P.z;
        s = sigm(G.w); o.w = s * R.w + (1.f - s) * P.w;
        dst[i] = o;
    }
}

// ------------------------- host launcher -----------------------------------
extern "C" void kernel_launch(void* const* d_in, const int* in_sizes, int n_in,
                              void* d_out, int out_size)
{
    (void)in_sizes; (void)n_in; (void)out_size;

    const float* x    = (const float*)d_in[0];
    const float* h0   = (const float*)d_in[1];
    const float* c0   = (const float*)d_in[2];
    const float* Wf0  = (const float*)d_in[3];
    const float* bf0  = (const float*)d_in[4];
    const float* Wb0  = (const float*)d_in[5];
    const float* bb0  = (const float*)d_in[6];
    const float* Wf1  = (const float*)d_in[7];
    const float* bf1  = (const float*)d_in[8];
    const float* Wb1  = (const float*)d_in[9];
    const float* bb1  = (const float*)d_in[10];
    const float* Wf2  = (const float*)d_in[11];
    const float* bf2  = (const float*)d_in[12];
    const float* Wb2  = (const float*)d_in[13];
    const float* bb2  = (const float*)d_in[14];
    const float* W_hw = (const float*)d_in[15];
    const float* b_hw = (const float*)d_in[16];

    float* out = (float*)d_out;
    float* hn  = out + (size_t)MROWS * 512;
    float* cn  = hn + 6 * BATCH * 256;

    float *zxf, *zxb, *buf0, *buf1;
    cudaGetSymbolAddress((void**)&zxf,  g_zxf);
    cudaGetSymbolAddress((void**)&zxb,  g_zxb);
    cudaGetSymbolAddress((void**)&buf0, g_buf0);
    cudaGetSymbolAddress((void**)&buf1, g_buf1);

    const dim3 g768(ZN / BN, MROWS / BM);   // (6, 256)
    const dim3 g512(512 / BN, MROWS / BM);  // (4, 256)
    const int n4 = (MROWS * 512) / 4;
    const int ewb = (n4 + 255) / 256;

    // ---- layer 0 ----
    sgemm_bias<<<g768, 256>>>(x, Wf0, bf0, zxf, MROWS, ZN, 256);
    sgemm_bias<<<g768, 256>>>(x, Wb0, bb0, zxb, MROWS, ZN, 256);
    recur17<<<256, 384>>>(Wf0 + (size_t)256 * ZN, Wb0 + (size_t)256 * ZN,
                          h0, c0, buf0, hn, cn, 0);
    // ---- layer 1 ----
    sgemm_bias<<<g768, 256>>>(buf0, Wf1, bf1, zxf, MROWS, ZN, 512);
    sgemm_bias<<<g768, 256>>>(buf0, Wb1, bb1, zxb, MROWS, ZN, 512);
    recur17<<<256, 384>>>(Wf1 + (size_t)512 * ZN, Wb1 + (size_t)512 * ZN,
                          h0, c0, buf1, hn, cn, 1);
    sgemm_bias<<<g512, 256>>>(buf1, W_hw, b_hw, zxf, MROWS, 512, 512);
    highway_ew<<<ewb, 256>>>((const float4*)zxf, (const float4*)buf1,
                             (const float4*)buf0, (float4*)buf1, n4);
    // ---- layer 2 ----
    sgemm_bias<<<g768, 256>>>(buf1, Wf2, bf2, zxf, MROWS, ZN, 512);
    sgemm_bias<<<g768, 256>>>(buf1, Wb2, bb2, zxb, MROWS, ZN, 512);
    recur17<<<256, 384>>>(Wf2 + (size_t)512 * ZN, Wb2 + (size_t)512 * ZN,
                          h0, c0, buf0, hn, cn, 2);
    sgemm_bias<<<g512, 256>>>(buf0, W_hw, b_hw, zxf, MROWS, 512, 512);
    highway_ew<<<ewb, 256>>>((const float4*)zxf, (const float4*)buf0,
                             (const float4*)buf1, (float4*)out, n4);
}